// round 11
// baseline (speedup 1.0000x reference)
#include <cuda_runtime.h>
#include <cuda_bf16.h>
#include <cstdint>

#define Bsz   2048
#define Hdim  1024
#define Lseq  96
#define Vsz   96

#define TM 128
#define TN 128
#define KC 32                 // bf16 K elements per chunk
#define STRIDE_B 80           // padded smem row: 32 bf16 (64B) + 16B pad
#define TILE_SMB (128 * STRIDE_B)          // 10240 B per operand tile
#define STAGE_SMB (4 * TILE_SMB)           // Ahi, Alo, Whi, Wlo
#define SMEM_TOTAL (2 * STAGE_SMB)         // 81920 B, double-buffered

// ---------------------------------------------------------------------------
// Device-global scratch (sanctioned scratch path; no allocations)
// ---------------------------------------------------------------------------
__device__ __nv_bfloat16 g_h0hi[2 * Bsz * Hdim];
__device__ __nv_bfloat16 g_h0lo[2 * Bsz * Hdim];
__device__ __nv_bfloat16 g_hshi[(size_t)Lseq * Bsz * Hdim];
__device__ __nv_bfloat16 g_hslo[(size_t)Lseq * Bsz * Hdim];
__device__ float g_h0f[Bsz * Hdim];
__device__ float g_h1f[Bsz * Hdim];
__device__ __nv_bfloat16 g_w0hh_hi[Hdim * Hdim], g_w0hh_lo[Hdim * Hdim];
__device__ __nv_bfloat16 g_w1ih_hi[Hdim * Hdim], g_w1ih_lo[Hdim * Hdim];
__device__ __nv_bfloat16 g_w1hh_hi[Hdim * Hdim], g_w1hh_lo[Hdim * Hdim];
__device__ __nv_bfloat16 g_fcw_hi[128 * Hdim], g_fcw_lo[128 * Hdim]; // padded to 128 rows
__device__ float g_bias0[Hdim], g_bias1[Hdim];

// ---------------------------------------------------------------------------
// PTX helpers: baseline sm_80+ instructions only (no arch-suffix features)
// ---------------------------------------------------------------------------
__device__ __forceinline__ uint32_t smem_to_u32(const void* p) {
    uint32_t a;
    asm("{ .reg .u64 t; cvta.to.shared.u64 t, %1; cvt.u32.u64 %0, t; }"
        : "=r"(a) : "l"(p));
    return a;
}
__device__ __forceinline__ void cp_async16(uint32_t dst, const void* src) {
    asm volatile("cp.async.cg.shared.global [%0], [%1], 16;"
                 :: "r"(dst), "l"(src));
}
__device__ __forceinline__ void cp_commit() {
    asm volatile("cp.async.commit_group;");
}
template <int N>
__device__ __forceinline__ void cp_wait() {
    asm volatile("cp.async.wait_group %0;" :: "n"(N));
}
__device__ __forceinline__ void ldsm_x4(uint32_t* r, uint32_t addr) {
    asm volatile("ldmatrix.sync.aligned.m8n8.x4.shared.b16 {%0,%1,%2,%3}, [%4];"
                 : "=r"(r[0]), "=r"(r[1]), "=r"(r[2]), "=r"(r[3]) : "r"(addr));
}
__device__ __forceinline__ void mma_bf16(float* d, const uint32_t* a,
                                         uint32_t b0, uint32_t b1) {
    asm volatile(
        "mma.sync.aligned.m16n8k16.row.col.f32.bf16.bf16.f32 "
        "{%0,%1,%2,%3}, {%4,%5,%6,%7}, {%8,%9}, {%0,%1,%2,%3};"
        : "+f"(d[0]), "+f"(d[1]), "+f"(d[2]), "+f"(d[3])
        : "r"(a[0]), "r"(a[1]), "r"(a[2]), "r"(a[3]), "r"(b0), "r"(b1));
}
__device__ __forceinline__ float tanh_fast(float v) {
    float e = __expf(2.0f * v);
    return 1.0f - __fdividef(2.0f, e + 1.0f);
}

// ---------------------------------------------------------------------------
// Main GEMM kernel (HMMA, bf16x3 split emulation of fp32).
//   D[m,n] = sum over 1-2 passes of  A[m,:] . W[n,:]
//   RNN epilogue: tanh(D + bias + x_t*wih) -> bf16 hi/lo (+ optional fp32)
//   FC  epilogue: D + fcb -> d_out[(b*L + t)*V + v]
// ---------------------------------------------------------------------------
template <bool IS_FC>
__global__ void __launch_bounds__(256, 1)
gemm_k(__nv_bfloat16* __restrict__ out_hi, __nv_bfloat16* __restrict__ out_lo,
       float* __restrict__ out_f,
       const __nv_bfloat16* __restrict__ A1h, const __nv_bfloat16* __restrict__ A1l,
       const __nv_bfloat16* __restrict__ W1h, const __nv_bfloat16* __restrict__ W1l, int kc1,
       const __nv_bfloat16* __restrict__ A2h, const __nv_bfloat16* __restrict__ A2l,
       const __nv_bfloat16* __restrict__ W2h, const __nv_bfloat16* __restrict__ W2l, int kc2,
       const float* __restrict__ bias, const float* __restrict__ xseq,
       const float* __restrict__ wih, int t)
{
    extern __shared__ char smem[];
    const uint32_t sb = smem_to_u32(smem);
    const int tid  = threadIdx.x;
    const int wid  = tid >> 5;
    const int lane = tid & 31;
    const int m0 = blockIdx.x * TM;
    const int n0 = IS_FC ? 0 : (blockIdx.y * TN);
    const int wm = (wid & 1) * 64;        // warp M offset within tile
    const int wn = (wid >> 1) * 32;       // warp N offset within tile

    float acc[4][4][4];
#pragma unroll
    for (int i = 0; i < 4; ++i)
#pragma unroll
        for (int j = 0; j < 4; ++j)
#pragma unroll
            for (int q = 0; q < 4; ++q) acc[i][j][q] = 0.0f;

    const int rounds = kc1 + kc2;

    // ---- async loader for round r into stage (r&1) ----
    auto load_round = [&](int r) {
        const bool p2 = (r >= kc1);
        const __nv_bfloat16* Ah = p2 ? A2h : A1h;
        const __nv_bfloat16* Al = p2 ? A2l : A1l;
        const __nv_bfloat16* Wh = p2 ? W2h : W1h;
        const __nv_bfloat16* Wl = p2 ? W2l : W1l;
        const int k0 = (p2 ? r - kc1 : r) * KC;
        const uint32_t sbase = sb + (r & 1) * STAGE_SMB;
#pragma unroll
        for (int i = 0; i < 2; ++i) {
            const int c   = tid + (i << 8);      // 0..511
            const int row = c >> 2;              // 128 rows, 4 x 16B chunks each
            const int c16 = c & 3;
            const size_t gA = (size_t)(m0 + row) * Hdim + k0 + c16 * 8;
            const size_t gW = (size_t)(n0 + row) * Hdim + k0 + c16 * 8;
            const uint32_t so = sbase + row * STRIDE_B + c16 * 16;
            cp_async16(so,                Ah + gA);
            cp_async16(so + TILE_SMB,     Al + gA);
            cp_async16(so + 2 * TILE_SMB, Wh + gW);
            cp_async16(so + 3 * TILE_SMB, Wl + gW);
        }
        cp_commit();
    };

    load_round(0);
    for (int r = 0; r < rounds; ++r) {
        if (r + 1 < rounds) { load_round(r + 1); cp_wait<1>(); }
        else                { cp_wait<0>(); }
        __syncthreads();

        const uint32_t sbase = sb + (r & 1) * STAGE_SMB;
        // ldmatrix lane addressing: rows = lane%16, 16B col block = lane/16
        const uint32_t aA = sbase + (wm + (lane & 15)) * STRIDE_B + ((lane >> 4) << 4);
        const uint32_t aB = sbase + 2 * TILE_SMB +
                            (wn + (lane & 15)) * STRIDE_B + ((lane >> 4) << 4);
#pragma unroll
        for (int ks = 0; ks < 2; ++ks) {        // two k16 steps per 32-chunk
            uint32_t ah[4][4], al[4][4];
#pragma unroll
            for (int im = 0; im < 4; ++im) {
                ldsm_x4(ah[im], aA + im * 16 * STRIDE_B + ks * 32);
                ldsm_x4(al[im], aA + TILE_SMB + im * 16 * STRIDE_B + ks * 32);
            }
            uint32_t bh[2][4], bl[2][4];
#pragma unroll
            for (int j2 = 0; j2 < 2; ++j2) {
                ldsm_x4(bh[j2], aB + j2 * 16 * STRIDE_B + ks * 32);
                ldsm_x4(bl[j2], aB + TILE_SMB + j2 * 16 * STRIDE_B + ks * 32);
            }
#pragma unroll
            for (int im = 0; im < 4; ++im)
#pragma unroll
                for (int jn = 0; jn < 4; ++jn) {
                    const int j2 = jn >> 1, js = jn & 1;
                    // hi*hi + hi*lo + lo*hi  (bf16x3 fp32 emulation)
                    mma_bf16(acc[im][jn], ah[im], bh[j2][js], bh[j2][js + 2]);
                    mma_bf16(acc[im][jn], ah[im], bl[j2][js], bl[j2][js + 2]);
                    mma_bf16(acc[im][jn], al[im], bh[j2][js], bh[j2][js + 2]);
                }
        }
        __syncthreads();   // stage reuse fence (next-next load overwrites it)
    }

    // ---- Epilogue ----
    const int lm  = lane >> 2;          // fragment row 0..7
    const int lc2 = (lane & 3) << 1;    // fragment col pair

    if (!IS_FC) {
#pragma unroll
        for (int im = 0; im < 4; ++im) {
            const int r0 = m0 + wm + im * 16 + lm;
            const int r1 = r0 + 8;
            float xv0 = 0.0f, xv1 = 0.0f;
            if (wih) {
                xv0 = __ldg(xseq + (size_t)r0 * Lseq + t);
                xv1 = __ldg(xseq + (size_t)r1 * Lseq + t);
            }
#pragma unroll
            for (int jn = 0; jn < 4; ++jn) {
                const int c = n0 + wn + jn * 8 + lc2;
                const float bb0 = __ldg(bias + c), bb1 = __ldg(bias + c + 1);
                float wi0 = 0.0f, wi1 = 0.0f;
                if (wih) { wi0 = __ldg(wih + c); wi1 = __ldg(wih + c + 1); }
                const float o00 = tanh_fast(acc[im][jn][0] + bb0 + xv0 * wi0);
                const float o01 = tanh_fast(acc[im][jn][1] + bb1 + xv0 * wi1);
                const float o10 = tanh_fast(acc[im][jn][2] + bb0 + xv1 * wi0);
                const float o11 = tanh_fast(acc[im][jn][3] + bb1 + xv1 * wi1);

                __nv_bfloat162 h0p, h1p, l0p, l1p;
                h0p.x = __float2bfloat16(o00);
                h0p.y = __float2bfloat16(o01);
                h1p.x = __float2bfloat16(o10);
                h1p.y = __float2bfloat16(o11);
                l0p.x = __float2bfloat16(o00 - __bfloat162float(h0p.x));
                l0p.y = __float2bfloat16(o01 - __bfloat162float(h0p.y));
                l1p.x = __float2bfloat16(o10 - __bfloat162float(h1p.x));
                l1p.y = __float2bfloat16(o11 - __bfloat162float(h1p.y));

                const size_t o0 = (size_t)r0 * Hdim + c;
                const size_t o1 = (size_t)r1 * Hdim + c;
                *(__nv_bfloat162*)(out_hi + o0) = h0p;
                *(__nv_bfloat162*)(out_hi + o1) = h1p;
                *(__nv_bfloat162*)(out_lo + o0) = l0p;
                *(__nv_bfloat162*)(out_lo + o1) = l1p;
                if (out_f) {
                    *(float2*)(out_f + o0) = make_float2(o00, o01);
                    *(float2*)(out_f + o1) = make_float2(o10, o11);
                }
            }
        }
    } else {
#pragma unroll
        for (int im = 0; im < 4; ++im) {
            const int r0 = m0 + wm + im * 16 + lm;
            const int r1 = r0 + 8;
            const int tt0 = r0 >> 11, b0i = r0 & (Bsz - 1);
            const int tt1 = r1 >> 11, b1i = r1 & (Bsz - 1);
#pragma unroll
            for (int jn = 0; jn < 4; ++jn) {
                const int c = wn + jn * 8 + lc2;
                if (c >= Vsz) continue;   // padded W cols 96..127: computed zeros
                const float bb0 = __ldg(bias + c), bb1 = __ldg(bias + c + 1);
                *(float2*)(out_f + ((size_t)b0i * Lseq + tt0) * Vsz + c) =
                    make_float2(acc[im][jn][0] + bb0, acc[im][jn][1] + bb1);
                *(float2*)(out_f + ((size_t)b1i * Lseq + tt1) * Vsz + c) =
                    make_float2(acc[im][jn][2] + bb0, acc[im][jn][3] + bb1);
            }
        }
    }
}

// ---------------------------------------------------------------------------
// Prep kernels
// ---------------------------------------------------------------------------
__global__ void split_k(__nv_bfloat16* __restrict__ hi, __nv_bfloat16* __restrict__ lo,
                        const float* __restrict__ src, int n)
{
    const int i = blockIdx.x * blockDim.x + threadIdx.x;
    if (i < n) {
        const float x = src[i];
        const __nv_bfloat16 h = __float2bfloat16(x);
        hi[i] = h;
        lo[i] = __float2bfloat16(x - __bfloat162float(h));
    }
}

// FC weight split, padded to 128 rows (rows 96..127 = 0)
__global__ void split_fc(__nv_bfloat16* __restrict__ hi, __nv_bfloat16* __restrict__ lo,
                         const float* __restrict__ src)
{
    const int i = blockIdx.x * blockDim.x + threadIdx.x;
    if (i < 128 * Hdim) {
        const int row = i >> 10;
        const float x = (row < Vsz) ? src[i] : 0.0f;
        const __nv_bfloat16 h = __float2bfloat16(x);
        hi[i] = h;
        lo[i] = __float2bfloat16(x - __bfloat162float(h));
    }
}

__global__ void bias_prep(float* __restrict__ b0, float* __restrict__ b1,
                          const float* a0, const float* c0,
                          const float* a1, const float* c1)
{
    const int i = threadIdx.x + blockIdx.x * blockDim.x;
    if (i < Hdim) { b0[i] = a0[i] + c0[i]; b1[i] = a1[i] + c1[i]; }
}

// t=0 layer0: h0 = tanh(x_0 * wih + bias0)   (h_prev = 0, no GEMM)
__global__ void l0_init(__nv_bfloat16* __restrict__ hhi, __nv_bfloat16* __restrict__ hlo,
                        const float* __restrict__ x, const float* __restrict__ wih,
                        const float* __restrict__ bias)
{
    const int i = blockIdx.x * blockDim.x + threadIdx.x;
    if (i < Bsz * Hdim) {
        const int b = i >> 10, n = i & (Hdim - 1);
        const float o = tanh_fast(x[b * Lseq + 0] * wih[n] + bias[n]);
        const __nv_bfloat16 h = __float2bfloat16(o);
        hhi[i] = h;
        hlo[i] = __float2bfloat16(o - __bfloat162float(h));
    }
}

// ---------------------------------------------------------------------------
// Sequential probability patch (unchanged from passing R4 kernel)
// ---------------------------------------------------------------------------
__global__ void adjust_kernel(float* __restrict__ out)
{
    const int gw   = (blockIdx.x * blockDim.x + threadIdx.x) >> 5;
    const int lane = threadIdx.x & 31;
    if (gw >= Bsz) return;
    const size_t base = (size_t)gw * Lseq * Vsz;

    int prev_arg = 0;
    for (int t = 0; t < Lseq; ++t) {
        const size_t r = base + (size_t)t * Vsz;
        float v0 = out[r + lane];
        float v1 = out[r + lane + 32];
        float v2 = out[r + lane + 64];

        float mv = v0; int mi = lane;
        if (v1 > mv) { mv = v1; mi = lane + 32; }
        if (v2 > mv) { mv = v2; mi = lane + 64; }
#pragma unroll
        for (int off = 16; off > 0; off >>= 1) {
            float ov = __shfl_xor_sync(0xffffffffu, mv, off);
            int   oi = __shfl_xor_sync(0xffffffffu, mi, off);
            if (ov > mv || (ov == mv && oi < mi)) { mv = ov; mi = oi; }
        }
        const int cur_arg = mi;

        if (t == 0) { prev_arg = cur_arg; continue; }

        bool modified = false;
        if (prev_arg == 0 && cur_arg != 1) {
            if (lane == 1) { v0 += 0.5f; out[r + 1] = v0; }
            modified = true;
        }
        if (t == Lseq - 1 && cur_arg == 0) {
            if (lane == 0) { v0 -= 0.5f; out[r + 0] = v0; }
            modified = true;
        }
        if (modified) {
            mv = v0; mi = lane;
            if (v1 > mv) { mv = v1; mi = lane + 32; }
            if (v2 > mv) { mv = v2; mi = lane + 64; }
#pragma unroll
            for (int off = 16; off > 0; off >>= 1) {
                float ov = __shfl_xor_sync(0xffffffffu, mv, off);
                int   oi = __shfl_xor_sync(0xffffffffu, mi, off);
                if (ov > mv || (ov == mv && oi < mi)) { mv = ov; mi = oi; }
            }
        }
        prev_arg = mi;
    }
}

__global__ void hidden_copy(float* __restrict__ out,
                            const float* __restrict__ h0,
                            const float* __restrict__ h1)
{
    const size_t i = (size_t)blockIdx.x * blockDim.x + threadIdx.x;
    if (i < (size_t)Bsz * Hdim) {
        out[i] = h0[i];
        out[(size_t)Bsz * Hdim + i] = h1[i];
    }
}

// ---------------------------------------------------------------------------
extern "C" void kernel_launch(void* const* d_in, const int* in_sizes, int n_in,
                              void* d_out, int out_size)
{
    (void)in_sizes; (void)n_in; (void)out_size;
    const float* x    = (const float*)d_in[0];
    const float* w0ih = (const float*)d_in[1];
    const float* w0hh = (const float*)d_in[2];
    const float* b0ih = (const float*)d_in[3];
    const float* b0hh = (const float*)d_in[4];
    const float* w1ih = (const float*)d_in[5];
    const float* w1hh = (const float*)d_in[6];
    const float* b1ih = (const float*)d_in[7];
    const float* b1hh = (const float*)d_in[8];
    const float* fcW  = (const float*)d_in[9];
    const float* fcb  = (const float*)d_in[10];
    float* out = (float*)d_out;

    __nv_bfloat16 *h0hi, *h0lo, *hshi, *hslo;
    __nv_bfloat16 *w0hhH, *w0hhL, *w1ihH, *w1ihL, *w1hhH, *w1hhL, *fcwH, *fcwL;
    float *h0f, *h1f, *bias0, *bias1;
    cudaGetSymbolAddress((void**)&h0hi, g_h0hi);
    cudaGetSymbolAddress((void**)&h0lo, g_h0lo);
    cudaGetSymbolAddress((void**)&hshi, g_hshi);
    cudaGetSymbolAddress((void**)&hslo, g_hslo);
    cudaGetSymbolAddress((void**)&h0f,  g_h0f);
    cudaGetSymbolAddress((void**)&h1f,  g_h1f);
    cudaGetSymbolAddress((void**)&w0hhH, g_w0hh_hi);
    cudaGetSymbolAddress((void**)&w0hhL, g_w0hh_lo);
    cudaGetSymbolAddress((void**)&w1ihH, g_w1ih_hi);
    cudaGetSymbolAddress((void**)&w1ihL, g_w1ih_lo);
    cudaGetSymbolAddress((void**)&w1hhH, g_w1hh_hi);
    cudaGetSymbolAddress((void**)&w1hhL, g_w1hh_lo);
    cudaGetSymbolAddress((void**)&fcwH, g_fcw_hi);
    cudaGetSymbolAddress((void**)&fcwL, g_fcw_lo);
    cudaGetSymbolAddress((void**)&bias0, g_bias0);
    cudaGetSymbolAddress((void**)&bias1, g_bias1);

    cudaFuncSetAttribute(gemm_k<false>, cudaFuncAttributeMaxDynamicSharedMemorySize, SMEM_TOTAL);
    cudaFuncSetAttribute(gemm_k<true>,  cudaFuncAttributeMaxDynamicSharedMemorySize, SMEM_TOTAL);

    // ---- Prep: split weights into bf16 hi/lo; combine biases ----
    const int nW = Hdim * Hdim;
    split_k<<<(nW + 255) / 256, 256>>>(w0hhH, w0hhL, w0hh, nW);
    split_k<<<(nW + 255) / 256, 256>>>(w1ihH, w1ihL, w1ih, nW);
    split_k<<<(nW + 255) / 256, 256>>>(w1hhH, w1hhL, w1hh, nW);
    split_fc<<<(128 * Hdim + 255) / 256, 256>>>(fcwH, fcwL, fcW);
    bias_prep<<<4, 256>>>(bias0, bias1, b0ih, b0hh, b1ih, b1hh);

    const dim3 grid_rnn(Bsz / TM, Hdim / TN);   // 16 x 8 = 128 CTAs
    const int  KCHUNKS = Hdim / KC;             // 32

    // ---- t=0 ----
    l0_init<<<(Bsz * Hdim + 255) / 256, 256>>>(h0hi, h0lo, x, w0ih, bias0);
    gemm_k<false><<<grid_rnn, 256, SMEM_TOTAL>>>(
        hshi, hslo, nullptr,
        h0hi, h0lo, w1ihH, w1ihL, KCHUNKS,
        nullptr, nullptr, nullptr, nullptr, 0,
        bias1, nullptr, nullptr, 0);

    // ---- t = 1..95 ----
    for (int t = 1; t < Lseq; ++t) {
        const int cur = t & 1, prv = cur ^ 1;
        __nv_bfloat16* h0hc = h0hi + (size_t)cur * Bsz * Hdim;
        __nv_bfloat16* h0lc = h0lo + (size_t)cur * Bsz * Hdim;
        const __nv_bfloat16* h0hp = h0hi + (size_t)prv * Bsz * Hdim;
        const __nv_bfloat16* h0lp = h0lo + (size_t)prv * Bsz * Hdim;
        const bool last = (t == Lseq - 1);

        // layer0: h0 = tanh(h0_prev@W0hh^T + x_t*w0ih + bias0)
        gemm_k<false><<<grid_rnn, 256, SMEM_TOTAL>>>(
            h0hc, h0lc, last ? h0f : nullptr,
            h0hp, h0lp, w0hhH, w0hhL, KCHUNKS,
            nullptr, nullptr, nullptr, nullptr, 0,
            bias0, x, w0ih, t);

        // layer1: h1 = tanh(h0@W1ih^T + h1_prev@W1hh^T + bias1)
        __nv_bfloat16* hsh = hshi + (size_t)t * Bsz * Hdim;
        __nv_bfloat16* hsl = hslo + (size_t)t * Bsz * Hdim;
        gemm_k<false><<<grid_rnn, 256, SMEM_TOTAL>>>(
            hsh, hsl, last ? h1f : nullptr,
            h0hc, h0lc, w1ihH, w1ihL, KCHUNKS,
            hshi + (size_t)(t - 1) * Bsz * Hdim,
            hslo + (size_t)(t - 1) * Bsz * Hdim, w1hhH, w1hhL, KCHUNKS,
            bias1, nullptr, nullptr, t);
    }

    // ---- FC over full h1 history -> logits (permuted to [b, t, v]) ----
    gemm_k<true><<<dim3(Lseq * Bsz / TM, 1), 256, SMEM_TOTAL>>>(
        nullptr, nullptr, out,
        hshi, hslo, fcwH, fcwL, KCHUNKS,
        nullptr, nullptr, nullptr, nullptr, 0,
        fcb, nullptr, nullptr, 0);

    // ---- sequential probability patch + hidden tail ----
    adjust_kernel<<<Bsz / 8, 256>>>(out);
    hidden_copy<<<(Bsz * Hdim + 255) / 256, 256>>>(
        out + (size_t)Bsz * Lseq * Vsz, h0f, h1f);
}

// round 13
// speedup vs baseline: 1.0002x; 1.0002x over previous
#include <cuda_runtime.h>
#include <cuda_bf16.h>
#include <cstdint>

#define Bsz   2048
#define Hdim  1024
#define Lseq  96
#define Vsz   96

#define TM 128
#define TN 128
#define KC 32                 // bf16 K elements per chunk
#define STRIDE_B 80           // padded smem row: 32 bf16 (64B) + 16B pad
#define TILE_SMB (128 * STRIDE_B)          // 10240 B per operand tile
#define STAGE_SMB (4 * TILE_SMB)           // Ahi, Alo, Whi, Wlo
#define SMEM_TOTAL (2 * STAGE_SMB)         // 81920 B, double-buffered

// ---------------------------------------------------------------------------
// Device-global scratch (sanctioned scratch path; no allocations)
// ---------------------------------------------------------------------------
__device__ __nv_bfloat16 g_h0hi[2 * Bsz * Hdim];
__device__ __nv_bfloat16 g_h0lo[2 * Bsz * Hdim];
__device__ __nv_bfloat16 g_hshi[(size_t)Lseq * Bsz * Hdim];
__device__ __nv_bfloat16 g_hslo[(size_t)Lseq * Bsz * Hdim];
__device__ float g_h0f[Bsz * Hdim];
__device__ float g_h1f[Bsz * Hdim];
__device__ __nv_bfloat16 g_w0hh_hi[Hdim * Hdim], g_w0hh_lo[Hdim * Hdim];
__device__ __nv_bfloat16 g_w1ih_hi[Hdim * Hdim], g_w1ih_lo[Hdim * Hdim];
__device__ __nv_bfloat16 g_w1hh_hi[Hdim * Hdim], g_w1hh_lo[Hdim * Hdim];
__device__ __nv_bfloat16 g_fcw_hi[128 * Hdim], g_fcw_lo[128 * Hdim]; // padded to 128 rows
__device__ float g_bias0[Hdim], g_bias1[Hdim];

// ---------------------------------------------------------------------------
// PTX helpers: baseline sm_80+ instructions only (no arch-suffix features)
// ---------------------------------------------------------------------------
__device__ __forceinline__ uint32_t smem_to_u32(const void* p) {
    uint32_t a;
    asm("{ .reg .u64 t; cvta.to.shared.u64 t, %1; cvt.u32.u64 %0, t; }"
        : "=r"(a) : "l"(p));
    return a;
}
__device__ __forceinline__ void cp_async16(uint32_t dst, const void* src) {
    asm volatile("cp.async.cg.shared.global [%0], [%1], 16;"
                 :: "r"(dst), "l"(src));
}
__device__ __forceinline__ void cp_commit() {
    asm volatile("cp.async.commit_group;");
}
template <int N>
__device__ __forceinline__ void cp_wait() {
    asm volatile("cp.async.wait_group %0;" :: "n"(N));
}
__device__ __forceinline__ void ldsm_x4(uint32_t* r, uint32_t addr) {
    asm volatile("ldmatrix.sync.aligned.m8n8.x4.shared.b16 {%0,%1,%2,%3}, [%4];"
                 : "=r"(r[0]), "=r"(r[1]), "=r"(r[2]), "=r"(r[3]) : "r"(addr));
}
__device__ __forceinline__ void mma_bf16(float* d, const uint32_t* a,
                                         uint32_t b0, uint32_t b1) {
    asm volatile(
        "mma.sync.aligned.m16n8k16.row.col.f32.bf16.bf16.f32 "
        "{%0,%1,%2,%3}, {%4,%5,%6,%7}, {%8,%9}, {%0,%1,%2,%3};"
        : "+f"(d[0]), "+f"(d[1]), "+f"(d[2]), "+f"(d[3])
        : "r"(a[0]), "r"(a[1]), "r"(a[2]), "r"(a[3]), "r"(b0), "r"(b1));
}
__device__ __forceinline__ float tanh_fast(float v) {
    float e = __expf(2.0f * v);
    return 1.0f - __fdividef(2.0f, e + 1.0f);
}

// ---------------------------------------------------------------------------
// Main GEMM kernel (HMMA, bf16x3 split emulation of fp32).
//   D[m,n] = sum over 1-2 passes of  A[m,:] . W[n,:]
//   RNN epilogue: tanh(D + bias + x_t*wih) -> bf16 hi/lo (+ optional fp32)
//   FC  epilogue: D + fcb -> d_out[(b*L + t)*V + v]
// ---------------------------------------------------------------------------
template <bool IS_FC>
__global__ void __launch_bounds__(256, 1)
gemm_k(__nv_bfloat16* __restrict__ out_hi, __nv_bfloat16* __restrict__ out_lo,
       float* __restrict__ out_f,
       const __nv_bfloat16* __restrict__ A1h, const __nv_bfloat16* __restrict__ A1l,
       const __nv_bfloat16* __restrict__ W1h, const __nv_bfloat16* __restrict__ W1l, int kc1,
       const __nv_bfloat16* __restrict__ A2h, const __nv_bfloat16* __restrict__ A2l,
       const __nv_bfloat16* __restrict__ W2h, const __nv_bfloat16* __restrict__ W2l, int kc2,
       const float* __restrict__ bias, const float* __restrict__ xseq,
       const float* __restrict__ wih, int t)
{
    extern __shared__ char smem[];
    const uint32_t sb = smem_to_u32(smem);
    const int tid  = threadIdx.x;
    const int wid  = tid >> 5;
    const int lane = tid & 31;
    const int m0 = blockIdx.x * TM;
    const int n0 = IS_FC ? 0 : (blockIdx.y * TN);
    const int wm = (wid & 1) * 64;        // warp M offset within tile
    const int wn = (wid >> 1) * 32;       // warp N offset within tile

    float acc[4][4][4];
#pragma unroll
    for (int i = 0; i < 4; ++i)
#pragma unroll
        for (int j = 0; j < 4; ++j)
#pragma unroll
            for (int q = 0; q < 4; ++q) acc[i][j][q] = 0.0f;

    const int rounds = kc1 + kc2;

    // ---- async loader for round r into stage (r&1) ----
    auto load_round = [&](int r) {
        const bool p2 = (r >= kc1);
        const __nv_bfloat16* Ah = p2 ? A2h : A1h;
        const __nv_bfloat16* Al = p2 ? A2l : A1l;
        const __nv_bfloat16* Wh = p2 ? W2h : W1h;
        const __nv_bfloat16* Wl = p2 ? W2l : W1l;
        const int k0 = (p2 ? r - kc1 : r) * KC;
        const uint32_t sbase = sb + (r & 1) * STAGE_SMB;
#pragma unroll
        for (int i = 0; i < 2; ++i) {
            const int c   = tid + (i << 8);      // 0..511
            const int row = c >> 2;              // 128 rows, 4 x 16B chunks each
            const int c16 = c & 3;
            const size_t gA = (size_t)(m0 + row) * Hdim + k0 + c16 * 8;
            const size_t gW = (size_t)(n0 + row) * Hdim + k0 + c16 * 8;
            const uint32_t so = sbase + row * STRIDE_B + c16 * 16;
            cp_async16(so,                Ah + gA);
            cp_async16(so + TILE_SMB,     Al + gA);
            cp_async16(so + 2 * TILE_SMB, Wh + gW);
            cp_async16(so + 3 * TILE_SMB, Wl + gW);
        }
        cp_commit();
    };

    load_round(0);
    for (int r = 0; r < rounds; ++r) {
        if (r + 1 < rounds) { load_round(r + 1); cp_wait<1>(); }
        else                { cp_wait<0>(); }
        __syncthreads();

        const uint32_t sbase = sb + (r & 1) * STAGE_SMB;
        // ldmatrix lane addressing: rows = lane%16, 16B col block = lane/16
        const uint32_t aA = sbase + (wm + (lane & 15)) * STRIDE_B + ((lane >> 4) << 4);
        const uint32_t aB = sbase + 2 * TILE_SMB +
                            (wn + (lane & 15)) * STRIDE_B + ((lane >> 4) << 4);
#pragma unroll
        for (int ks = 0; ks < 2; ++ks) {        // two k16 steps per 32-chunk
            uint32_t ah[4][4], al[4][4];
#pragma unroll
            for (int im = 0; im < 4; ++im) {
                ldsm_x4(ah[im], aA + im * 16 * STRIDE_B + ks * 32);
                ldsm_x4(al[im], aA + TILE_SMB + im * 16 * STRIDE_B + ks * 32);
            }
            uint32_t bh[2][4], bl[2][4];
#pragma unroll
            for (int j2 = 0; j2 < 2; ++j2) {
                ldsm_x4(bh[j2], aB + j2 * 16 * STRIDE_B + ks * 32);
                ldsm_x4(bl[j2], aB + TILE_SMB + j2 * 16 * STRIDE_B + ks * 32);
            }
#pragma unroll
            for (int im = 0; im < 4; ++im)
#pragma unroll
                for (int jn = 0; jn < 4; ++jn) {
                    const int j2 = jn >> 1, js = jn & 1;
                    // hi*hi + hi*lo + lo*hi  (bf16x3 fp32 emulation)
                    mma_bf16(acc[im][jn], ah[im], bh[j2][js], bh[j2][js + 2]);
                    mma_bf16(acc[im][jn], ah[im], bl[j2][js], bl[j2][js + 2]);
                    mma_bf16(acc[im][jn], al[im], bh[j2][js], bh[j2][js + 2]);
                }
        }
        __syncthreads();   // stage reuse fence (next-next load overwrites it)
    }

    // ---- Epilogue ----
    const int lm  = lane >> 2;          // fragment row 0..7
    const int lc2 = (lane & 3) << 1;    // fragment col pair

    if (!IS_FC) {
#pragma unroll
        for (int im = 0; im < 4; ++im) {
            const int r0 = m0 + wm + im * 16 + lm;
            const int r1 = r0 + 8;
            float xv0 = 0.0f, xv1 = 0.0f;
            if (wih) {
                xv0 = __ldg(xseq + (size_t)r0 * Lseq + t);
                xv1 = __ldg(xseq + (size_t)r1 * Lseq + t);
            }
#pragma unroll
            for (int jn = 0; jn < 4; ++jn) {
                const int c = n0 + wn + jn * 8 + lc2;
                const float bb0 = __ldg(bias + c), bb1 = __ldg(bias + c + 1);
                float wi0 = 0.0f, wi1 = 0.0f;
                if (wih) { wi0 = __ldg(wih + c); wi1 = __ldg(wih + c + 1); }
                const float o00 = tanh_fast(acc[im][jn][0] + bb0 + xv0 * wi0);
                const float o01 = tanh_fast(acc[im][jn][1] + bb1 + xv0 * wi1);
                const float o10 = tanh_fast(acc[im][jn][2] + bb0 + xv1 * wi0);
                const float o11 = tanh_fast(acc[im][jn][3] + bb1 + xv1 * wi1);

                __nv_bfloat162 h0p, h1p, l0p, l1p;
                h0p.x = __float2bfloat16(o00);
                h0p.y = __float2bfloat16(o01);
                h1p.x = __float2bfloat16(o10);
                h1p.y = __float2bfloat16(o11);
                l0p.x = __float2bfloat16(o00 - __bfloat162float(h0p.x));
                l0p.y = __float2bfloat16(o01 - __bfloat162float(h0p.y));
                l1p.x = __float2bfloat16(o10 - __bfloat162float(h1p.x));
                l1p.y = __float2bfloat16(o11 - __bfloat162float(h1p.y));

                const size_t o0 = (size_t)r0 * Hdim + c;
                const size_t o1 = (size_t)r1 * Hdim + c;
                *(__nv_bfloat162*)(out_hi + o0) = h0p;
                *(__nv_bfloat162*)(out_hi + o1) = h1p;
                *(__nv_bfloat162*)(out_lo + o0) = l0p;
                *(__nv_bfloat162*)(out_lo + o1) = l1p;
                if (out_f) {
                    *(float2*)(out_f + o0) = make_float2(o00, o01);
                    *(float2*)(out_f + o1) = make_float2(o10, o11);
                }
            }
        }
    } else {
#pragma unroll
        for (int im = 0; im < 4; ++im) {
            const int r0 = m0 + wm + im * 16 + lm;
            const int r1 = r0 + 8;
            const int tt0 = r0 >> 11, b0i = r0 & (Bsz - 1);
            const int tt1 = r1 >> 11, b1i = r1 & (Bsz - 1);
#pragma unroll
            for (int jn = 0; jn < 4; ++jn) {
                const int c = wn + jn * 8 + lc2;
                if (c >= Vsz) continue;   // padded W cols 96..127: computed zeros
                const float bb0 = __ldg(bias + c), bb1 = __ldg(bias + c + 1);
                *(float2*)(out_f + ((size_t)b0i * Lseq + tt0) * Vsz + c) =
                    make_float2(acc[im][jn][0] + bb0, acc[im][jn][1] + bb1);
                *(float2*)(out_f + ((size_t)b1i * Lseq + tt1) * Vsz + c) =
                    make_float2(acc[im][jn][2] + bb0, acc[im][jn][3] + bb1);
            }
        }
    }
}

// ---------------------------------------------------------------------------
// Prep kernels
// ---------------------------------------------------------------------------
__global__ void split_k(__nv_bfloat16* __restrict__ hi, __nv_bfloat16* __restrict__ lo,
                        const float* __restrict__ src, int n)
{
    const int i = blockIdx.x * blockDim.x + threadIdx.x;
    if (i < n) {
        const float x = src[i];
        const __nv_bfloat16 h = __float2bfloat16(x);
        hi[i] = h;
        lo[i] = __float2bfloat16(x - __bfloat162float(h));
    }
}

// FC weight split, padded to 128 rows (rows 96..127 = 0)
__global__ void split_fc(__nv_bfloat16* __restrict__ hi, __nv_bfloat16* __restrict__ lo,
                         const float* __restrict__ src)
{
    const int i = blockIdx.x * blockDim.x + threadIdx.x;
    if (i < 128 * Hdim) {
        const int row = i >> 10;
        const float x = (row < Vsz) ? src[i] : 0.0f;
        const __nv_bfloat16 h = __float2bfloat16(x);
        hi[i] = h;
        lo[i] = __float2bfloat16(x - __bfloat162float(h));
    }
}

__global__ void bias_prep(float* __restrict__ b0, float* __restrict__ b1,
                          const float* a0, const float* c0,
                          const float* a1, const float* c1)
{
    const int i = threadIdx.x + blockIdx.x * blockDim.x;
    if (i < Hdim) { b0[i] = a0[i] + c0[i]; b1[i] = a1[i] + c1[i]; }
}

// t=0 layer0: h0 = tanh(x_0 * wih + bias0)   (h_prev = 0, no GEMM)
__global__ void l0_init(__nv_bfloat16* __restrict__ hhi, __nv_bfloat16* __restrict__ hlo,
                        const float* __restrict__ x, const float* __restrict__ wih,
                        const float* __restrict__ bias)
{
    const int i = blockIdx.x * blockDim.x + threadIdx.x;
    if (i < Bsz * Hdim) {
        const int b = i >> 10, n = i & (Hdim - 1);
        const float o = tanh_fast(x[b * Lseq + 0] * wih[n] + bias[n]);
        const __nv_bfloat16 h = __float2bfloat16(o);
        hhi[i] = h;
        hlo[i] = __float2bfloat16(o - __bfloat162float(h));
    }
}

// ---------------------------------------------------------------------------
// Sequential probability patch (unchanged from passing R4 kernel)
// ---------------------------------------------------------------------------
__global__ void adjust_kernel(float* __restrict__ out)
{
    const int gw   = (blockIdx.x * blockDim.x + threadIdx.x) >> 5;
    const int lane = threadIdx.x & 31;
    if (gw >= Bsz) return;
    const size_t base = (size_t)gw * Lseq * Vsz;

    int prev_arg = 0;
    for (int t = 0; t < Lseq; ++t) {
        const size_t r = base + (size_t)t * Vsz;
        float v0 = out[r + lane];
        float v1 = out[r + lane + 32];
        float v2 = out[r + lane + 64];

        float mv = v0; int mi = lane;
        if (v1 > mv) { mv = v1; mi = lane + 32; }
        if (v2 > mv) { mv = v2; mi = lane + 64; }
#pragma unroll
        for (int off = 16; off > 0; off >>= 1) {
            float ov = __shfl_xor_sync(0xffffffffu, mv, off);
            int   oi = __shfl_xor_sync(0xffffffffu, mi, off);
            if (ov > mv || (ov == mv && oi < mi)) { mv = ov; mi = oi; }
        }
        const int cur_arg = mi;

        if (t == 0) { prev_arg = cur_arg; continue; }

        bool modified = false;
        if (prev_arg == 0 && cur_arg != 1) {
            if (lane == 1) { v0 += 0.5f; out[r + 1] = v0; }
            modified = true;
        }
        if (t == Lseq - 1 && cur_arg == 0) {
            if (lane == 0) { v0 -= 0.5f; out[r + 0] = v0; }
            modified = true;
        }
        if (modified) {
            mv = v0; mi = lane;
            if (v1 > mv) { mv = v1; mi = lane + 32; }
            if (v2 > mv) { mv = v2; mi = lane + 64; }
#pragma unroll
            for (int off = 16; off > 0; off >>= 1) {
                float ov = __shfl_xor_sync(0xffffffffu, mv, off);
                int   oi = __shfl_xor_sync(0xffffffffu, mi, off);
                if (ov > mv || (ov == mv && oi < mi)) { mv = ov; mi = oi; }
            }
        }
        prev_arg = mi;
    }
}

__global__ void hidden_copy(float* __restrict__ out,
                            const float* __restrict__ h0,
                            const float* __restrict__ h1)
{
    const size_t i = (size_t)blockIdx.x * blockDim.x + threadIdx.x;
    if (i < (size_t)Bsz * Hdim) {
        out[i] = h0[i];
        out[(size_t)Bsz * Hdim + i] = h1[i];
    }
}

// ---------------------------------------------------------------------------
extern "C" void kernel_launch(void* const* d_in, const int* in_sizes, int n_in,
                              void* d_out, int out_size)
{
    (void)in_sizes; (void)n_in; (void)out_size;
    const float* x    = (const float*)d_in[0];
    const float* w0ih = (const float*)d_in[1];
    const float* w0hh = (const float*)d_in[2];
    const float* b0ih = (const float*)d_in[3];
    const float* b0hh = (const float*)d_in[4];
    const float* w1ih = (const float*)d_in[5];
    const float* w1hh = (const float*)d_in[6];
    const float* b1ih = (const float*)d_in[7];
    const float* b1hh = (const float*)d_in[8];
    const float* fcW  = (const float*)d_in[9];
    const float* fcb  = (const float*)d_in[10];
    float* out = (float*)d_out;

    __nv_bfloat16 *h0hi, *h0lo, *hshi, *hslo;
    __nv_bfloat16 *w0hhH, *w0hhL, *w1ihH, *w1ihL, *w1hhH, *w1hhL, *fcwH, *fcwL;
    float *h0f, *h1f, *bias0, *bias1;
    cudaGetSymbolAddress((void**)&h0hi, g_h0hi);
    cudaGetSymbolAddress((void**)&h0lo, g_h0lo);
    cudaGetSymbolAddress((void**)&hshi, g_hshi);
    cudaGetSymbolAddress((void**)&hslo, g_hslo);
    cudaGetSymbolAddress((void**)&h0f,  g_h0f);
    cudaGetSymbolAddress((void**)&h1f,  g_h1f);
    cudaGetSymbolAddress((void**)&w0hhH, g_w0hh_hi);
    cudaGetSymbolAddress((void**)&w0hhL, g_w0hh_lo);
    cudaGetSymbolAddress((void**)&w1ihH, g_w1ih_hi);
    cudaGetSymbolAddress((void**)&w1ihL, g_w1ih_lo);
    cudaGetSymbolAddress((void**)&w1hhH, g_w1hh_hi);
    cudaGetSymbolAddress((void**)&w1hhL, g_w1hh_lo);
    cudaGetSymbolAddress((void**)&fcwH, g_fcw_hi);
    cudaGetSymbolAddress((void**)&fcwL, g_fcw_lo);
    cudaGetSymbolAddress((void**)&bias0, g_bias0);
    cudaGetSymbolAddress((void**)&bias1, g_bias1);

    cudaFuncSetAttribute(gemm_k<false>, cudaFuncAttributeMaxDynamicSharedMemorySize, SMEM_TOTAL);
    cudaFuncSetAttribute(gemm_k<true>,  cudaFuncAttributeMaxDynamicSharedMemorySize, SMEM_TOTAL);

    // ---- Prep: split weights into bf16 hi/lo; combine biases ----
    const int nW = Hdim * Hdim;
    split_k<<<(nW + 255) / 256, 256>>>(w0hhH, w0hhL, w0hh, nW);
    split_k<<<(nW + 255) / 256, 256>>>(w1ihH, w1ihL, w1ih, nW);
    split_k<<<(nW + 255) / 256, 256>>>(w1hhH, w1hhL, w1hh, nW);
    split_fc<<<(128 * Hdim + 255) / 256, 256>>>(fcwH, fcwL, fcW);
    bias_prep<<<4, 256>>>(bias0, bias1, b0ih, b0hh, b1ih, b1hh);

    const dim3 grid_rnn(Bsz / TM, Hdim / TN);   // 16 x 8 = 128 CTAs
    const int  KCHUNKS = Hdim / KC;             // 32

    // ---- t=0 ----
    l0_init<<<(Bsz * Hdim + 255) / 256, 256>>>(h0hi, h0lo, x, w0ih, bias0);
    gemm_k<false><<<grid_rnn, 256, SMEM_TOTAL>>>(
        hshi, hslo, nullptr,
        h0hi, h0lo, w1ihH, w1ihL, KCHUNKS,
        nullptr, nullptr, nullptr, nullptr, 0,
        bias1, nullptr, nullptr, 0);

    // ---- t = 1..95 ----
    for (int t = 1; t < Lseq; ++t) {
        const int cur = t & 1, prv = cur ^ 1;
        __nv_bfloat16* h0hc = h0hi + (size_t)cur * Bsz * Hdim;
        __nv_bfloat16* h0lc = h0lo + (size_t)cur * Bsz * Hdim;
        const __nv_bfloat16* h0hp = h0hi + (size_t)prv * Bsz * Hdim;
        const __nv_bfloat16* h0lp = h0lo + (size_t)prv * Bsz * Hdim;
        const bool last = (t == Lseq - 1);

        // layer0: h0 = tanh(h0_prev@W0hh^T + x_t*w0ih + bias0)
        gemm_k<false><<<grid_rnn, 256, SMEM_TOTAL>>>(
            h0hc, h0lc, last ? h0f : nullptr,
            h0hp, h0lp, w0hhH, w0hhL, KCHUNKS,
            nullptr, nullptr, nullptr, nullptr, 0,
            bias0, x, w0ih, t);

        // layer1: h1 = tanh(h0@W1ih^T + h1_prev@W1hh^T + bias1)
        __nv_bfloat16* hsh = hshi + (size_t)t * Bsz * Hdim;
        __nv_bfloat16* hsl = hslo + (size_t)t * Bsz * Hdim;
        gemm_k<false><<<grid_rnn, 256, SMEM_TOTAL>>>(
            hsh, hsl, last ? h1f : nullptr,
            h0hc, h0lc, w1ihH, w1ihL, KCHUNKS,
            hshi + (size_t)(t - 1) * Bsz * Hdim,
            hslo + (size_t)(t - 1) * Bsz * Hdim, w1hhH, w1hhL, KCHUNKS,
            bias1, nullptr, nullptr, t);
    }

    // ---- FC over full h1 history -> logits (permuted to [b, t, v]) ----
    gemm_k<true><<<dim3(Lseq * Bsz / TM, 1), 256, SMEM_TOTAL>>>(
        nullptr, nullptr, out,
        hshi, hslo, fcwH, fcwL, KCHUNKS,
        nullptr, nullptr, nullptr, nullptr, 0,
        fcb, nullptr, nullptr, 0);

    // ---- sequential probability patch + hidden tail ----
    adjust_kernel<<<Bsz / 8, 256>>>(out);
    hidden_copy<<<(Bsz * Hdim + 255) / 256, 256>>>(
        out + (size_t)Bsz * Lseq * Vsz, h0f, h1f);
}

// round 15
// speedup vs baseline: 1.0004x; 1.0002x over previous
#include <cuda_runtime.h>
#include <cuda_bf16.h>
#include <cstdint>

#define Bsz   2048
#define Hdim  1024
#define Lseq  96
#define Vsz   96

#define TM 128
#define TN 128
#define KC 32                 // bf16 K elements per chunk
#define STRIDE_B 80           // padded smem row: 32 bf16 (64B) + 16B pad
#define TILE_SMB (128 * STRIDE_B)          // 10240 B per operand tile
#define STAGE_SMB (4 * TILE_SMB)           // Ahi, Alo, Whi, Wlo
#define SMEM_TOTAL (2 * STAGE_SMB)         // 81920 B, double-buffered

// ---------------------------------------------------------------------------
// Device-global scratch (sanctioned scratch path; no allocations)
// ---------------------------------------------------------------------------
__device__ __nv_bfloat16 g_h0hi[2 * Bsz * Hdim];
__device__ __nv_bfloat16 g_h0lo[2 * Bsz * Hdim];
__device__ __nv_bfloat16 g_hshi[(size_t)Lseq * Bsz * Hdim];
__device__ __nv_bfloat16 g_hslo[(size_t)Lseq * Bsz * Hdim];
__device__ float g_h0f[Bsz * Hdim];
__device__ float g_h1f[Bsz * Hdim];
__device__ __nv_bfloat16 g_w0hh_hi[Hdim * Hdim], g_w0hh_lo[Hdim * Hdim];
__device__ __nv_bfloat16 g_w1ih_hi[Hdim * Hdim], g_w1ih_lo[Hdim * Hdim];
__device__ __nv_bfloat16 g_w1hh_hi[Hdim * Hdim], g_w1hh_lo[Hdim * Hdim];
__device__ __nv_bfloat16 g_fcw_hi[128 * Hdim], g_fcw_lo[128 * Hdim]; // padded to 128 rows
__device__ float g_bias0[Hdim], g_bias1[Hdim];

// ---------------------------------------------------------------------------
// PTX helpers: baseline sm_80+ instructions only (no arch-suffix features)
// ---------------------------------------------------------------------------
__device__ __forceinline__ uint32_t smem_to_u32(const void* p) {
    uint32_t a;
    asm("{ .reg .u64 t; cvta.to.shared.u64 t, %1; cvt.u32.u64 %0, t; }"
        : "=r"(a) : "l"(p));
    return a;
}
__device__ __forceinline__ void cp_async16(uint32_t dst, const void* src) {
    asm volatile("cp.async.cg.shared.global [%0], [%1], 16;"
                 :: "r"(dst), "l"(src));
}
__device__ __forceinline__ void cp_commit() {
    asm volatile("cp.async.commit_group;");
}
template <int N>
__device__ __forceinline__ void cp_wait() {
    asm volatile("cp.async.wait_group %0;" :: "n"(N));
}
__device__ __forceinline__ void ldsm_x4(uint32_t* r, uint32_t addr) {
    asm volatile("ldmatrix.sync.aligned.m8n8.x4.shared.b16 {%0,%1,%2,%3}, [%4];"
                 : "=r"(r[0]), "=r"(r[1]), "=r"(r[2]), "=r"(r[3]) : "r"(addr));
}
__device__ __forceinline__ void mma_bf16(float* d, const uint32_t* a,
                                         uint32_t b0, uint32_t b1) {
    asm volatile(
        "mma.sync.aligned.m16n8k16.row.col.f32.bf16.bf16.f32 "
        "{%0,%1,%2,%3}, {%4,%5,%6,%7}, {%8,%9}, {%0,%1,%2,%3};"
        : "+f"(d[0]), "+f"(d[1]), "+f"(d[2]), "+f"(d[3])
        : "r"(a[0]), "r"(a[1]), "r"(a[2]), "r"(a[3]), "r"(b0), "r"(b1));
}
__device__ __forceinline__ float tanh_fast(float v) {
    float e = __expf(2.0f * v);
    return 1.0f - __fdividef(2.0f, e + 1.0f);
}

// ---------------------------------------------------------------------------
// Main GEMM kernel (HMMA, bf16x3 split emulation of fp32).
//   D[m,n] = sum over 1-2 passes of  A[m,:] . W[n,:]
//   RNN epilogue: tanh(D + bias + x_t*wih) -> bf16 hi/lo (+ optional fp32)
//   FC  epilogue: D + fcb -> d_out[(b*L + t)*V + v]
// ---------------------------------------------------------------------------
template <bool IS_FC>
__global__ void __launch_bounds__(256, 1)
gemm_k(__nv_bfloat16* __restrict__ out_hi, __nv_bfloat16* __restrict__ out_lo,
       float* __restrict__ out_f,
       const __nv_bfloat16* __restrict__ A1h, const __nv_bfloat16* __restrict__ A1l,
       const __nv_bfloat16* __restrict__ W1h, const __nv_bfloat16* __restrict__ W1l, int kc1,
       const __nv_bfloat16* __restrict__ A2h, const __nv_bfloat16* __restrict__ A2l,
       const __nv_bfloat16* __restrict__ W2h, const __nv_bfloat16* __restrict__ W2l, int kc2,
       const float* __restrict__ bias, const float* __restrict__ xseq,
       const float* __restrict__ wih, int t)
{
    extern __shared__ char smem[];
    const uint32_t sb = smem_to_u32(smem);
    const int tid  = threadIdx.x;
    const int wid  = tid >> 5;
    const int lane = tid & 31;
    const int m0 = blockIdx.x * TM;
    const int n0 = IS_FC ? 0 : (blockIdx.y * TN);
    const int wm = (wid & 1) * 64;        // warp M offset within tile
    const int wn = (wid >> 1) * 32;       // warp N offset within tile

    float acc[4][4][4];
#pragma unroll
    for (int i = 0; i < 4; ++i)
#pragma unroll
        for (int j = 0; j < 4; ++j)
#pragma unroll
            for (int q = 0; q < 4; ++q) acc[i][j][q] = 0.0f;

    const int rounds = kc1 + kc2;

    // ---- async loader for round r into stage (r&1) ----
    auto load_round = [&](int r) {
        const bool p2 = (r >= kc1);
        const __nv_bfloat16* Ah = p2 ? A2h : A1h;
        const __nv_bfloat16* Al = p2 ? A2l : A1l;
        const __nv_bfloat16* Wh = p2 ? W2h : W1h;
        const __nv_bfloat16* Wl = p2 ? W2l : W1l;
        const int k0 = (p2 ? r - kc1 : r) * KC;
        const uint32_t sbase = sb + (r & 1) * STAGE_SMB;
#pragma unroll
        for (int i = 0; i < 2; ++i) {
            const int c   = tid + (i << 8);      // 0..511
            const int row = c >> 2;              // 128 rows, 4 x 16B chunks each
            const int c16 = c & 3;
            const size_t gA = (size_t)(m0 + row) * Hdim + k0 + c16 * 8;
            const size_t gW = (size_t)(n0 + row) * Hdim + k0 + c16 * 8;
            const uint32_t so = sbase + row * STRIDE_B + c16 * 16;
            cp_async16(so,                Ah + gA);
            cp_async16(so + TILE_SMB,     Al + gA);
            cp_async16(so + 2 * TILE_SMB, Wh + gW);
            cp_async16(so + 3 * TILE_SMB, Wl + gW);
        }
        cp_commit();
    };

    load_round(0);
    for (int r = 0; r < rounds; ++r) {
        if (r + 1 < rounds) { load_round(r + 1); cp_wait<1>(); }
        else                { cp_wait<0>(); }
        __syncthreads();

        const uint32_t sbase = sb + (r & 1) * STAGE_SMB;
        // ldmatrix lane addressing: rows = lane%16, 16B col block = lane/16
        const uint32_t aA = sbase + (wm + (lane & 15)) * STRIDE_B + ((lane >> 4) << 4);
        const uint32_t aB = sbase + 2 * TILE_SMB +
                            (wn + (lane & 15)) * STRIDE_B + ((lane >> 4) << 4);
#pragma unroll
        for (int ks = 0; ks < 2; ++ks) {        // two k16 steps per 32-chunk
            uint32_t ah[4][4], al[4][4];
#pragma unroll
            for (int im = 0; im < 4; ++im) {
                ldsm_x4(ah[im], aA + im * 16 * STRIDE_B + ks * 32);
                ldsm_x4(al[im], aA + TILE_SMB + im * 16 * STRIDE_B + ks * 32);
            }
            uint32_t bh[2][4], bl[2][4];
#pragma unroll
            for (int j2 = 0; j2 < 2; ++j2) {
                ldsm_x4(bh[j2], aB + j2 * 16 * STRIDE_B + ks * 32);
                ldsm_x4(bl[j2], aB + TILE_SMB + j2 * 16 * STRIDE_B + ks * 32);
            }
#pragma unroll
            for (int im = 0; im < 4; ++im)
#pragma unroll
                for (int jn = 0; jn < 4; ++jn) {
                    const int j2 = jn >> 1, js = jn & 1;
                    // hi*hi + hi*lo + lo*hi  (bf16x3 fp32 emulation)
                    mma_bf16(acc[im][jn], ah[im], bh[j2][js], bh[j2][js + 2]);
                    mma_bf16(acc[im][jn], ah[im], bl[j2][js], bl[j2][js + 2]);
                    mma_bf16(acc[im][jn], al[im], bh[j2][js], bh[j2][js + 2]);
                }
        }
        __syncthreads();   // stage reuse fence (next-next load overwrites it)
    }

    // ---- Epilogue ----
    const int lm  = lane >> 2;          // fragment row 0..7
    const int lc2 = (lane & 3) << 1;    // fragment col pair

    if (!IS_FC) {
#pragma unroll
        for (int im = 0; im < 4; ++im) {
            const int r0 = m0 + wm + im * 16 + lm;
            const int r1 = r0 + 8;
            float xv0 = 0.0f, xv1 = 0.0f;
            if (wih) {
                xv0 = __ldg(xseq + (size_t)r0 * Lseq + t);
                xv1 = __ldg(xseq + (size_t)r1 * Lseq + t);
            }
#pragma unroll
            for (int jn = 0; jn < 4; ++jn) {
                const int c = n0 + wn + jn * 8 + lc2;
                const float bb0 = __ldg(bias + c), bb1 = __ldg(bias + c + 1);
                float wi0 = 0.0f, wi1 = 0.0f;
                if (wih) { wi0 = __ldg(wih + c); wi1 = __ldg(wih + c + 1); }
                const float o00 = tanh_fast(acc[im][jn][0] + bb0 + xv0 * wi0);
                const float o01 = tanh_fast(acc[im][jn][1] + bb1 + xv0 * wi1);
                const float o10 = tanh_fast(acc[im][jn][2] + bb0 + xv1 * wi0);
                const float o11 = tanh_fast(acc[im][jn][3] + bb1 + xv1 * wi1);

                __nv_bfloat162 h0p, h1p, l0p, l1p;
                h0p.x = __float2bfloat16(o00);
                h0p.y = __float2bfloat16(o01);
                h1p.x = __float2bfloat16(o10);
                h1p.y = __float2bfloat16(o11);
                l0p.x = __float2bfloat16(o00 - __bfloat162float(h0p.x));
                l0p.y = __float2bfloat16(o01 - __bfloat162float(h0p.y));
                l1p.x = __float2bfloat16(o10 - __bfloat162float(h1p.x));
                l1p.y = __float2bfloat16(o11 - __bfloat162float(h1p.y));

                const size_t o0 = (size_t)r0 * Hdim + c;
                const size_t o1 = (size_t)r1 * Hdim + c;
                *(__nv_bfloat162*)(out_hi + o0) = h0p;
                *(__nv_bfloat162*)(out_hi + o1) = h1p;
                *(__nv_bfloat162*)(out_lo + o0) = l0p;
                *(__nv_bfloat162*)(out_lo + o1) = l1p;
                if (out_f) {
                    *(float2*)(out_f + o0) = make_float2(o00, o01);
                    *(float2*)(out_f + o1) = make_float2(o10, o11);
                }
            }
        }
    } else {
#pragma unroll
        for (int im = 0; im < 4; ++im) {
            const int r0 = m0 + wm + im * 16 + lm;
            const int r1 = r0 + 8;
            const int tt0 = r0 >> 11, b0i = r0 & (Bsz - 1);
            const int tt1 = r1 >> 11, b1i = r1 & (Bsz - 1);
#pragma unroll
            for (int jn = 0; jn < 4; ++jn) {
                const int c = wn + jn * 8 + lc2;
                if (c >= Vsz) continue;   // padded W cols 96..127: computed zeros
                const float bb0 = __ldg(bias + c), bb1 = __ldg(bias + c + 1);
                *(float2*)(out_f + ((size_t)b0i * Lseq + tt0) * Vsz + c) =
                    make_float2(acc[im][jn][0] + bb0, acc[im][jn][1] + bb1);
                *(float2*)(out_f + ((size_t)b1i * Lseq + tt1) * Vsz + c) =
                    make_float2(acc[im][jn][2] + bb0, acc[im][jn][3] + bb1);
            }
        }
    }
}

// ---------------------------------------------------------------------------
// Prep kernels
// ---------------------------------------------------------------------------
__global__ void split_k(__nv_bfloat16* __restrict__ hi, __nv_bfloat16* __restrict__ lo,
                        const float* __restrict__ src, int n)
{
    const int i = blockIdx.x * blockDim.x + threadIdx.x;
    if (i < n) {
        const float x = src[i];
        const __nv_bfloat16 h = __float2bfloat16(x);
        hi[i] = h;
        lo[i] = __float2bfloat16(x - __bfloat162float(h));
    }
}

// FC weight split, padded to 128 rows (rows 96..127 = 0)
__global__ void split_fc(__nv_bfloat16* __restrict__ hi, __nv_bfloat16* __restrict__ lo,
                         const float* __restrict__ src)
{
    const int i = blockIdx.x * blockDim.x + threadIdx.x;
    if (i < 128 * Hdim) {
        const int row = i >> 10;
        const float x = (row < Vsz) ? src[i] : 0.0f;
        const __nv_bfloat16 h = __float2bfloat16(x);
        hi[i] = h;
        lo[i] = __float2bfloat16(x - __bfloat162float(h));
    }
}

__global__ void bias_prep(float* __restrict__ b0, float* __restrict__ b1,
                          const float* a0, const float* c0,
                          const float* a1, const float* c1)
{
    const int i = threadIdx.x + blockIdx.x * blockDim.x;
    if (i < Hdim) { b0[i] = a0[i] + c0[i]; b1[i] = a1[i] + c1[i]; }
}

// t=0 layer0: h0 = tanh(x_0 * wih + bias0)   (h_prev = 0, no GEMM)
__global__ void l0_init(__nv_bfloat16* __restrict__ hhi, __nv_bfloat16* __restrict__ hlo,
                        const float* __restrict__ x, const float* __restrict__ wih,
                        const float* __restrict__ bias)
{
    const int i = blockIdx.x * blockDim.x + threadIdx.x;
    if (i < Bsz * Hdim) {
        const int b = i >> 10, n = i & (Hdim - 1);
        const float o = tanh_fast(x[b * Lseq + 0] * wih[n] + bias[n]);
        const __nv_bfloat16 h = __float2bfloat16(o);
        hhi[i] = h;
        hlo[i] = __float2bfloat16(o - __bfloat162float(h));
    }
}

// ---------------------------------------------------------------------------
// Sequential probability patch (unchanged from passing R4 kernel)
// ---------------------------------------------------------------------------
__global__ void adjust_kernel(float* __restrict__ out)
{
    const int gw   = (blockIdx.x * blockDim.x + threadIdx.x) >> 5;
    const int lane = threadIdx.x & 31;
    if (gw >= Bsz) return;
    const size_t base = (size_t)gw * Lseq * Vsz;

    int prev_arg = 0;
    for (int t = 0; t < Lseq; ++t) {
        const size_t r = base + (size_t)t * Vsz;
        float v0 = out[r + lane];
        float v1 = out[r + lane + 32];
        float v2 = out[r + lane + 64];

        float mv = v0; int mi = lane;
        if (v1 > mv) { mv = v1; mi = lane + 32; }
        if (v2 > mv) { mv = v2; mi = lane + 64; }
#pragma unroll
        for (int off = 16; off > 0; off >>= 1) {
            float ov = __shfl_xor_sync(0xffffffffu, mv, off);
            int   oi = __shfl_xor_sync(0xffffffffu, mi, off);
            if (ov > mv || (ov == mv && oi < mi)) { mv = ov; mi = oi; }
        }
        const int cur_arg = mi;

        if (t == 0) { prev_arg = cur_arg; continue; }

        bool modified = false;
        if (prev_arg == 0 && cur_arg != 1) {
            if (lane == 1) { v0 += 0.5f; out[r + 1] = v0; }
            modified = true;
        }
        if (t == Lseq - 1 && cur_arg == 0) {
            if (lane == 0) { v0 -= 0.5f; out[r + 0] = v0; }
            modified = true;
        }
        if (modified) {
            mv = v0; mi = lane;
            if (v1 > mv) { mv = v1; mi = lane + 32; }
            if (v2 > mv) { mv = v2; mi = lane + 64; }
#pragma unroll
            for (int off = 16; off > 0; off >>= 1) {
                float ov = __shfl_xor_sync(0xffffffffu, mv, off);
                int   oi = __shfl_xor_sync(0xffffffffu, mi, off);
                if (ov > mv || (ov == mv && oi < mi)) { mv = ov; mi = oi; }
            }
        }
        prev_arg = mi;
    }
}

__global__ void hidden_copy(float* __restrict__ out,
                            const float* __restrict__ h0,
                            const float* __restrict__ h1)
{
    const size_t i = (size_t)blockIdx.x * blockDim.x + threadIdx.x;
    if (i < (size_t)Bsz * Hdim) {
        out[i] = h0[i];
        out[(size_t)Bsz * Hdim + i] = h1[i];
    }
}

// ---------------------------------------------------------------------------
extern "C" void kernel_launch(void* const* d_in, const int* in_sizes, int n_in,
                              void* d_out, int out_size)
{
    (void)in_sizes; (void)n_in; (void)out_size;
    const float* x    = (const float*)d_in[0];
    const float* w0ih = (const float*)d_in[1];
    const float* w0hh = (const float*)d_in[2];
    const float* b0ih = (const float*)d_in[3];
    const float* b0hh = (const float*)d_in[4];
    const float* w1ih = (const float*)d_in[5];
    const float* w1hh = (const float*)d_in[6];
    const float* b1ih = (const float*)d_in[7];
    const float* b1hh = (const float*)d_in[8];
    const float* fcW  = (const float*)d_in[9];
    const float* fcb  = (const float*)d_in[10];
    float* out = (float*)d_out;

    __nv_bfloat16 *h0hi, *h0lo, *hshi, *hslo;
    __nv_bfloat16 *w0hhH, *w0hhL, *w1ihH, *w1ihL, *w1hhH, *w1hhL, *fcwH, *fcwL;
    float *h0f, *h1f, *bias0, *bias1;
    cudaGetSymbolAddress((void**)&h0hi, g_h0hi);
    cudaGetSymbolAddress((void**)&h0lo, g_h0lo);
    cudaGetSymbolAddress((void**)&hshi, g_hshi);
    cudaGetSymbolAddress((void**)&hslo, g_hslo);
    cudaGetSymbolAddress((void**)&h0f,  g_h0f);
    cudaGetSymbolAddress((void**)&h1f,  g_h1f);
    cudaGetSymbolAddress((void**)&w0hhH, g_w0hh_hi);
    cudaGetSymbolAddress((void**)&w0hhL, g_w0hh_lo);
    cudaGetSymbolAddress((void**)&w1ihH, g_w1ih_hi);
    cudaGetSymbolAddress((void**)&w1ihL, g_w1ih_lo);
    cudaGetSymbolAddress((void**)&w1hhH, g_w1hh_hi);
    cudaGetSymbolAddress((void**)&w1hhL, g_w1hh_lo);
    cudaGetSymbolAddress((void**)&fcwH, g_fcw_hi);
    cudaGetSymbolAddress((void**)&fcwL, g_fcw_lo);
    cudaGetSymbolAddress((void**)&bias0, g_bias0);
    cudaGetSymbolAddress((void**)&bias1, g_bias1);

    cudaFuncSetAttribute(gemm_k<false>, cudaFuncAttributeMaxDynamicSharedMemorySize, SMEM_TOTAL);
    cudaFuncSetAttribute(gemm_k<true>,  cudaFuncAttributeMaxDynamicSharedMemorySize, SMEM_TOTAL);

    // ---- Prep: split weights into bf16 hi/lo; combine biases ----
    const int nW = Hdim * Hdim;
    split_k<<<(nW + 255) / 256, 256>>>(w0hhH, w0hhL, w0hh, nW);
    split_k<<<(nW + 255) / 256, 256>>>(w1ihH, w1ihL, w1ih, nW);
    split_k<<<(nW + 255) / 256, 256>>>(w1hhH, w1hhL, w1hh, nW);
    split_fc<<<(128 * Hdim + 255) / 256, 256>>>(fcwH, fcwL, fcW);
    bias_prep<<<4, 256>>>(bias0, bias1, b0ih, b0hh, b1ih, b1hh);

    const dim3 grid_rnn(Bsz / TM, Hdim / TN);   // 16 x 8 = 128 CTAs
    const int  KCHUNKS = Hdim / KC;             // 32

    // ---- t=0 ----
    l0_init<<<(Bsz * Hdim + 255) / 256, 256>>>(h0hi, h0lo, x, w0ih, bias0);
    gemm_k<false><<<grid_rnn, 256, SMEM_TOTAL>>>(
        hshi, hslo, nullptr,
        h0hi, h0lo, w1ihH, w1ihL, KCHUNKS,
        nullptr, nullptr, nullptr, nullptr, 0,
        bias1, nullptr, nullptr, 0);

    // ---- t = 1..95 ----
    for (int t = 1; t < Lseq; ++t) {
        const int cur = t & 1, prv = cur ^ 1;
        __nv_bfloat16* h0hc = h0hi + (size_t)cur * Bsz * Hdim;
        __nv_bfloat16* h0lc = h0lo + (size_t)cur * Bsz * Hdim;
        const __nv_bfloat16* h0hp = h0hi + (size_t)prv * Bsz * Hdim;
        const __nv_bfloat16* h0lp = h0lo + (size_t)prv * Bsz * Hdim;
        const bool last = (t == Lseq - 1);

        // layer0: h0 = tanh(h0_prev@W0hh^T + x_t*w0ih + bias0)
        gemm_k<false><<<grid_rnn, 256, SMEM_TOTAL>>>(
            h0hc, h0lc, last ? h0f : nullptr,
            h0hp, h0lp, w0hhH, w0hhL, KCHUNKS,
            nullptr, nullptr, nullptr, nullptr, 0,
            bias0, x, w0ih, t);

        // layer1: h1 = tanh(h0@W1ih^T + h1_prev@W1hh^T + bias1)
        __nv_bfloat16* hsh = hshi + (size_t)t * Bsz * Hdim;
        __nv_bfloat16* hsl = hslo + (size_t)t * Bsz * Hdim;
        gemm_k<false><<<grid_rnn, 256, SMEM_TOTAL>>>(
            hsh, hsl, last ? h1f : nullptr,
            h0hc, h0lc, w1ihH, w1ihL, KCHUNKS,
            hshi + (size_t)(t - 1) * Bsz * Hdim,
            hslo + (size_t)(t - 1) * Bsz * Hdim, w1hhH, w1hhL, KCHUNKS,
            bias1, nullptr, nullptr, t);
    }

    // ---- FC over full h1 history -> logits (permuted to [b, t, v]) ----
    gemm_k<true><<<dim3(Lseq * Bsz / TM, 1), 256, SMEM_TOTAL>>>(
        nullptr, nullptr, out,
        hshi, hslo, fcwH, fcwL, KCHUNKS,
        nullptr, nullptr, nullptr, nullptr, 0,
        fcb, nullptr, nullptr, 0);

    // ---- sequential probability patch + hidden tail ----
    adjust_kernel<<<Bsz / 8, 256>>>(out);
    hidden_copy<<<(Bsz * Hdim + 255) / 256, 256>>>(
        out + (size_t)Bsz * Lseq * Vsz, h0f, h1f);
}

// round 16
// speedup vs baseline: 1.0025x; 1.0021x over previous
#include <cuda_runtime.h>
#include <cuda_bf16.h>
#include <cstdint>

#define Bsz   2048
#define Hdim  1024
#define Lseq  96
#define Vsz   96

#define TM 128
#define TN 128
#define KC 32                 // bf16 K elements per chunk
#define STRIDE_B 80           // padded smem row: 32 bf16 (64B) + 16B pad
#define TILE_SMB (128 * STRIDE_B)          // 10240 B per operand tile
#define STAGE_SMB (4 * TILE_SMB)           // Ahi, Alo, Whi, Wlo
#define SMEM_TOTAL (2 * STAGE_SMB)         // 81920 B, double-buffered

// ---------------------------------------------------------------------------
// Device-global scratch (sanctioned scratch path; no allocations)
// ---------------------------------------------------------------------------
__device__ __nv_bfloat16 g_h0hi[2 * Bsz * Hdim];
__device__ __nv_bfloat16 g_h0lo[2 * Bsz * Hdim];
__device__ __nv_bfloat16 g_hshi[(size_t)Lseq * Bsz * Hdim];
__device__ __nv_bfloat16 g_hslo[(size_t)Lseq * Bsz * Hdim];
__device__ float g_h0f[Bsz * Hdim];
__device__ float g_h1f[Bsz * Hdim];
__device__ __nv_bfloat16 g_w0hh_hi[Hdim * Hdim], g_w0hh_lo[Hdim * Hdim];
__device__ __nv_bfloat16 g_w1ih_hi[Hdim * Hdim], g_w1ih_lo[Hdim * Hdim];
__device__ __nv_bfloat16 g_w1hh_hi[Hdim * Hdim], g_w1hh_lo[Hdim * Hdim];
__device__ __nv_bfloat16 g_fcw_hi[128 * Hdim], g_fcw_lo[128 * Hdim]; // padded to 128 rows
__device__ float g_bias0[Hdim], g_bias1[Hdim];

// ---------------------------------------------------------------------------
// PTX helpers: baseline sm_80+ instructions only (no arch-suffix features)
// ---------------------------------------------------------------------------
__device__ __forceinline__ uint32_t smem_to_u32(const void* p) {
    uint32_t a;
    asm("{ .reg .u64 t; cvta.to.shared.u64 t, %1; cvt.u32.u64 %0, t; }"
        : "=r"(a) : "l"(p));
    return a;
}
__device__ __forceinline__ void cp_async16(uint32_t dst, const void* src) {
    asm volatile("cp.async.cg.shared.global [%0], [%1], 16;"
                 :: "r"(dst), "l"(src));
}
__device__ __forceinline__ void cp_commit() {
    asm volatile("cp.async.commit_group;");
}
template <int N>
__device__ __forceinline__ void cp_wait() {
    asm volatile("cp.async.wait_group %0;" :: "n"(N));
}
__device__ __forceinline__ void ldsm_x4(uint32_t* r, uint32_t addr) {
    asm volatile("ldmatrix.sync.aligned.m8n8.x4.shared.b16 {%0,%1,%2,%3}, [%4];"
                 : "=r"(r[0]), "=r"(r[1]), "=r"(r[2]), "=r"(r[3]) : "r"(addr));
}
__device__ __forceinline__ void mma_bf16(float* d, const uint32_t* a,
                                         uint32_t b0, uint32_t b1) {
    asm volatile(
        "mma.sync.aligned.m16n8k16.row.col.f32.bf16.bf16.f32 "
        "{%0,%1,%2,%3}, {%4,%5,%6,%7}, {%8,%9}, {%0,%1,%2,%3};"
        : "+f"(d[0]), "+f"(d[1]), "+f"(d[2]), "+f"(d[3])
        : "r"(a[0]), "r"(a[1]), "r"(a[2]), "r"(a[3]), "r"(b0), "r"(b1));
}
__device__ __forceinline__ float tanh_fast(float v) {
    float e = __expf(2.0f * v);
    return 1.0f - __fdividef(2.0f, e + 1.0f);
}

// ---------------------------------------------------------------------------
// Main GEMM kernel (HMMA, bf16x3 split emulation of fp32).
//   D[m,n] = sum over 1-2 passes of  A[m,:] . W[n,:]
//   RNN epilogue: tanh(D + bias + x_t*wih) -> bf16 hi/lo (+ optional fp32)
//   FC  epilogue: D + fcb -> d_out[(b*L + t)*V + v]
// ---------------------------------------------------------------------------
template <bool IS_FC>
__global__ void __launch_bounds__(256, 1)
gemm_k(__nv_bfloat16* __restrict__ out_hi, __nv_bfloat16* __restrict__ out_lo,
       float* __restrict__ out_f,
       const __nv_bfloat16* __restrict__ A1h, const __nv_bfloat16* __restrict__ A1l,
       const __nv_bfloat16* __restrict__ W1h, const __nv_bfloat16* __restrict__ W1l, int kc1,
       const __nv_bfloat16* __restrict__ A2h, const __nv_bfloat16* __restrict__ A2l,
       const __nv_bfloat16* __restrict__ W2h, const __nv_bfloat16* __restrict__ W2l, int kc2,
       const float* __restrict__ bias, const float* __restrict__ xseq,
       const float* __restrict__ wih, int t)
{
    extern __shared__ char smem[];
    const uint32_t sb = smem_to_u32(smem);
    const int tid  = threadIdx.x;
    const int wid  = tid >> 5;
    const int lane = tid & 31;
    const int m0 = blockIdx.x * TM;
    const int n0 = IS_FC ? 0 : (blockIdx.y * TN);
    const int wm = (wid & 1) * 64;        // warp M offset within tile
    const int wn = (wid >> 1) * 32;       // warp N offset within tile

    float acc[4][4][4];
#pragma unroll
    for (int i = 0; i < 4; ++i)
#pragma unroll
        for (int j = 0; j < 4; ++j)
#pragma unroll
            for (int q = 0; q < 4; ++q) acc[i][j][q] = 0.0f;

    const int rounds = kc1 + kc2;

    // ---- async loader for round r into stage (r&1) ----
    auto load_round = [&](int r) {
        const bool p2 = (r >= kc1);
        const __nv_bfloat16* Ah = p2 ? A2h : A1h;
        const __nv_bfloat16* Al = p2 ? A2l : A1l;
        const __nv_bfloat16* Wh = p2 ? W2h : W1h;
        const __nv_bfloat16* Wl = p2 ? W2l : W1l;
        const int k0 = (p2 ? r - kc1 : r) * KC;
        const uint32_t sbase = sb + (r & 1) * STAGE_SMB;
#pragma unroll
        for (int i = 0; i < 2; ++i) {
            const int c   = tid + (i << 8);      // 0..511
            const int row = c >> 2;              // 128 rows, 4 x 16B chunks each
            const int c16 = c & 3;
            const size_t gA = (size_t)(m0 + row) * Hdim + k0 + c16 * 8;
            const size_t gW = (size_t)(n0 + row) * Hdim + k0 + c16 * 8;
            const uint32_t so = sbase + row * STRIDE_B + c16 * 16;
            cp_async16(so,                Ah + gA);
            cp_async16(so + TILE_SMB,     Al + gA);
            cp_async16(so + 2 * TILE_SMB, Wh + gW);
            cp_async16(so + 3 * TILE_SMB, Wl + gW);
        }
        cp_commit();
    };

    load_round(0);
    for (int r = 0; r < rounds; ++r) {
        if (r + 1 < rounds) { load_round(r + 1); cp_wait<1>(); }
        else                { cp_wait<0>(); }
        __syncthreads();

        const uint32_t sbase = sb + (r & 1) * STAGE_SMB;
        // ldmatrix lane addressing: rows = lane%16, 16B col block = lane/16
        const uint32_t aA = sbase + (wm + (lane & 15)) * STRIDE_B + ((lane >> 4) << 4);
        const uint32_t aB = sbase + 2 * TILE_SMB +
                            (wn + (lane & 15)) * STRIDE_B + ((lane >> 4) << 4);
#pragma unroll
        for (int ks = 0; ks < 2; ++ks) {        // two k16 steps per 32-chunk
            uint32_t ah[4][4], al[4][4];
#pragma unroll
            for (int im = 0; im < 4; ++im) {
                ldsm_x4(ah[im], aA + im * 16 * STRIDE_B + ks * 32);
                ldsm_x4(al[im], aA + TILE_SMB + im * 16 * STRIDE_B + ks * 32);
            }
            uint32_t bh[2][4], bl[2][4];
#pragma unroll
            for (int j2 = 0; j2 < 2; ++j2) {
                ldsm_x4(bh[j2], aB + j2 * 16 * STRIDE_B + ks * 32);
                ldsm_x4(bl[j2], aB + TILE_SMB + j2 * 16 * STRIDE_B + ks * 32);
            }
#pragma unroll
            for (int im = 0; im < 4; ++im)
#pragma unroll
                for (int jn = 0; jn < 4; ++jn) {
                    const int j2 = jn >> 1, js = jn & 1;
                    // hi*hi + hi*lo + lo*hi  (bf16x3 fp32 emulation)
                    mma_bf16(acc[im][jn], ah[im], bh[j2][js], bh[j2][js + 2]);
                    mma_bf16(acc[im][jn], ah[im], bl[j2][js], bl[j2][js + 2]);
                    mma_bf16(acc[im][jn], al[im], bh[j2][js], bh[j2][js + 2]);
                }
        }
        __syncthreads();   // stage reuse fence (next-next load overwrites it)
    }

    // ---- Epilogue ----
    const int lm  = lane >> 2;          // fragment row 0..7
    const int lc2 = (lane & 3) << 1;    // fragment col pair

    if (!IS_FC) {
#pragma unroll
        for (int im = 0; im < 4; ++im) {
            const int r0 = m0 + wm + im * 16 + lm;
            const int r1 = r0 + 8;
            float xv0 = 0.0f, xv1 = 0.0f;
            if (wih) {
                xv0 = __ldg(xseq + (size_t)r0 * Lseq + t);
                xv1 = __ldg(xseq + (size_t)r1 * Lseq + t);
            }
#pragma unroll
            for (int jn = 0; jn < 4; ++jn) {
                const int c = n0 + wn + jn * 8 + lc2;
                const float bb0 = __ldg(bias + c), bb1 = __ldg(bias + c + 1);
                float wi0 = 0.0f, wi1 = 0.0f;
                if (wih) { wi0 = __ldg(wih + c); wi1 = __ldg(wih + c + 1); }
                const float o00 = tanh_fast(acc[im][jn][0] + bb0 + xv0 * wi0);
                const float o01 = tanh_fast(acc[im][jn][1] + bb1 + xv0 * wi1);
                const float o10 = tanh_fast(acc[im][jn][2] + bb0 + xv1 * wi0);
                const float o11 = tanh_fast(acc[im][jn][3] + bb1 + xv1 * wi1);

                __nv_bfloat162 h0p, h1p, l0p, l1p;
                h0p.x = __float2bfloat16(o00);
                h0p.y = __float2bfloat16(o01);
                h1p.x = __float2bfloat16(o10);
                h1p.y = __float2bfloat16(o11);
                l0p.x = __float2bfloat16(o00 - __bfloat162float(h0p.x));
                l0p.y = __float2bfloat16(o01 - __bfloat162float(h0p.y));
                l1p.x = __float2bfloat16(o10 - __bfloat162float(h1p.x));
                l1p.y = __float2bfloat16(o11 - __bfloat162float(h1p.y));

                const size_t o0 = (size_t)r0 * Hdim + c;
                const size_t o1 = (size_t)r1 * Hdim + c;
                *(__nv_bfloat162*)(out_hi + o0) = h0p;
                *(__nv_bfloat162*)(out_hi + o1) = h1p;
                *(__nv_bfloat162*)(out_lo + o0) = l0p;
                *(__nv_bfloat162*)(out_lo + o1) = l1p;
                if (out_f) {
                    *(float2*)(out_f + o0) = make_float2(o00, o01);
                    *(float2*)(out_f + o1) = make_float2(o10, o11);
                }
            }
        }
    } else {
#pragma unroll
        for (int im = 0; im < 4; ++im) {
            const int r0 = m0 + wm + im * 16 + lm;
            const int r1 = r0 + 8;
            const int tt0 = r0 >> 11, b0i = r0 & (Bsz - 1);
            const int tt1 = r1 >> 11, b1i = r1 & (Bsz - 1);
#pragma unroll
            for (int jn = 0; jn < 4; ++jn) {
                const int c = wn + jn * 8 + lc2;
                if (c >= Vsz) continue;   // padded W cols 96..127: computed zeros
                const float bb0 = __ldg(bias + c), bb1 = __ldg(bias + c + 1);
                *(float2*)(out_f + ((size_t)b0i * Lseq + tt0) * Vsz + c) =
                    make_float2(acc[im][jn][0] + bb0, acc[im][jn][1] + bb1);
                *(float2*)(out_f + ((size_t)b1i * Lseq + tt1) * Vsz + c) =
                    make_float2(acc[im][jn][2] + bb0, acc[im][jn][3] + bb1);
            }
        }
    }
}

// ---------------------------------------------------------------------------
// Prep kernels
// ---------------------------------------------------------------------------
__global__ void split_k(__nv_bfloat16* __restrict__ hi, __nv_bfloat16* __restrict__ lo,
                        const float* __restrict__ src, int n)
{
    const int i = blockIdx.x * blockDim.x + threadIdx.x;
    if (i < n) {
        const float x = src[i];
        const __nv_bfloat16 h = __float2bfloat16(x);
        hi[i] = h;
        lo[i] = __float2bfloat16(x - __bfloat162float(h));
    }
}

// FC weight split, padded to 128 rows (rows 96..127 = 0)
__global__ void split_fc(__nv_bfloat16* __restrict__ hi, __nv_bfloat16* __restrict__ lo,
                         const float* __restrict__ src)
{
    const int i = blockIdx.x * blockDim.x + threadIdx.x;
    if (i < 128 * Hdim) {
        const int row = i >> 10;
        const float x = (row < Vsz) ? src[i] : 0.0f;
        const __nv_bfloat16 h = __float2bfloat16(x);
        hi[i] = h;
        lo[i] = __float2bfloat16(x - __bfloat162float(h));
    }
}

__global__ void bias_prep(float* __restrict__ b0, float* __restrict__ b1,
                          const float* a0, const float* c0,
                          const float* a1, const float* c1)
{
    const int i = threadIdx.x + blockIdx.x * blockDim.x;
    if (i < Hdim) { b0[i] = a0[i] + c0[i]; b1[i] = a1[i] + c1[i]; }
}

// t=0 layer0: h0 = tanh(x_0 * wih + bias0)   (h_prev = 0, no GEMM)
__global__ void l0_init(__nv_bfloat16* __restrict__ hhi, __nv_bfloat16* __restrict__ hlo,
                        const float* __restrict__ x, const float* __restrict__ wih,
                        const float* __restrict__ bias)
{
    const int i = blockIdx.x * blockDim.x + threadIdx.x;
    if (i < Bsz * Hdim) {
        const int b = i >> 10, n = i & (Hdim - 1);
        const float o = tanh_fast(x[b * Lseq + 0] * wih[n] + bias[n]);
        const __nv_bfloat16 h = __float2bfloat16(o);
        hhi[i] = h;
        hlo[i] = __float2bfloat16(o - __bfloat162float(h));
    }
}

// ---------------------------------------------------------------------------
// Sequential probability patch (unchanged from passing R4 kernel)
// ---------------------------------------------------------------------------
__global__ void adjust_kernel(float* __restrict__ out)
{
    const int gw   = (blockIdx.x * blockDim.x + threadIdx.x) >> 5;
    const int lane = threadIdx.x & 31;
    if (gw >= Bsz) return;
    const size_t base = (size_t)gw * Lseq * Vsz;

    int prev_arg = 0;
    for (int t = 0; t < Lseq; ++t) {
        const size_t r = base + (size_t)t * Vsz;
        float v0 = out[r + lane];
        float v1 = out[r + lane + 32];
        float v2 = out[r + lane + 64];

        float mv = v0; int mi = lane;
        if (v1 > mv) { mv = v1; mi = lane + 32; }
        if (v2 > mv) { mv = v2; mi = lane + 64; }
#pragma unroll
        for (int off = 16; off > 0; off >>= 1) {
            float ov = __shfl_xor_sync(0xffffffffu, mv, off);
            int   oi = __shfl_xor_sync(0xffffffffu, mi, off);
            if (ov > mv || (ov == mv && oi < mi)) { mv = ov; mi = oi; }
        }
        const int cur_arg = mi;

        if (t == 0) { prev_arg = cur_arg; continue; }

        bool modified = false;
        if (prev_arg == 0 && cur_arg != 1) {
            if (lane == 1) { v0 += 0.5f; out[r + 1] = v0; }
            modified = true;
        }
        if (t == Lseq - 1 && cur_arg == 0) {
            if (lane == 0) { v0 -= 0.5f; out[r + 0] = v0; }
            modified = true;
        }
        if (modified) {
            mv = v0; mi = lane;
            if (v1 > mv) { mv = v1; mi = lane + 32; }
            if (v2 > mv) { mv = v2; mi = lane + 64; }
#pragma unroll
            for (int off = 16; off > 0; off >>= 1) {
                float ov = __shfl_xor_sync(0xffffffffu, mv, off);
                int   oi = __shfl_xor_sync(0xffffffffu, mi, off);
                if (ov > mv || (ov == mv && oi < mi)) { mv = ov; mi = oi; }
            }
        }
        prev_arg = mi;
    }
}

__global__ void hidden_copy(float* __restrict__ out,
                            const float* __restrict__ h0,
                            const float* __restrict__ h1)
{
    const size_t i = (size_t)blockIdx.x * blockDim.x + threadIdx.x;
    if (i < (size_t)Bsz * Hdim) {
        out[i] = h0[i];
        out[(size_t)Bsz * Hdim + i] = h1[i];
    }
}

// ---------------------------------------------------------------------------
extern "C" void kernel_launch(void* const* d_in, const int* in_sizes, int n_in,
                              void* d_out, int out_size)
{
    (void)in_sizes; (void)n_in; (void)out_size;
    const float* x    = (const float*)d_in[0];
    const float* w0ih = (const float*)d_in[1];
    const float* w0hh = (const float*)d_in[2];
    const float* b0ih = (const float*)d_in[3];
    const float* b0hh = (const float*)d_in[4];
    const float* w1ih = (const float*)d_in[5];
    const float* w1hh = (const float*)d_in[6];
    const float* b1ih = (const float*)d_in[7];
    const float* b1hh = (const float*)d_in[8];
    const float* fcW  = (const float*)d_in[9];
    const float* fcb  = (const float*)d_in[10];
    float* out = (float*)d_out;

    __nv_bfloat16 *h0hi, *h0lo, *hshi, *hslo;
    __nv_bfloat16 *w0hhH, *w0hhL, *w1ihH, *w1ihL, *w1hhH, *w1hhL, *fcwH, *fcwL;
    float *h0f, *h1f, *bias0, *bias1;
    cudaGetSymbolAddress((void**)&h0hi, g_h0hi);
    cudaGetSymbolAddress((void**)&h0lo, g_h0lo);
    cudaGetSymbolAddress((void**)&hshi, g_hshi);
    cudaGetSymbolAddress((void**)&hslo, g_hslo);
    cudaGetSymbolAddress((void**)&h0f,  g_h0f);
    cudaGetSymbolAddress((void**)&h1f,  g_h1f);
    cudaGetSymbolAddress((void**)&w0hhH, g_w0hh_hi);
    cudaGetSymbolAddress((void**)&w0hhL, g_w0hh_lo);
    cudaGetSymbolAddress((void**)&w1ihH, g_w1ih_hi);
    cudaGetSymbolAddress((void**)&w1ihL, g_w1ih_lo);
    cudaGetSymbolAddress((void**)&w1hhH, g_w1hh_hi);
    cudaGetSymbolAddress((void**)&w1hhL, g_w1hh_lo);
    cudaGetSymbolAddress((void**)&fcwH, g_fcw_hi);
    cudaGetSymbolAddress((void**)&fcwL, g_fcw_lo);
    cudaGetSymbolAddress((void**)&bias0, g_bias0);
    cudaGetSymbolAddress((void**)&bias1, g_bias1);

    cudaFuncSetAttribute(gemm_k<false>, cudaFuncAttributeMaxDynamicSharedMemorySize, SMEM_TOTAL);
    cudaFuncSetAttribute(gemm_k<true>,  cudaFuncAttributeMaxDynamicSharedMemorySize, SMEM_TOTAL);

    // ---- Prep: split weights into bf16 hi/lo; combine biases ----
    const int nW = Hdim * Hdim;
    split_k<<<(nW + 255) / 256, 256>>>(w0hhH, w0hhL, w0hh, nW);
    split_k<<<(nW + 255) / 256, 256>>>(w1ihH, w1ihL, w1ih, nW);
    split_k<<<(nW + 255) / 256, 256>>>(w1hhH, w1hhL, w1hh, nW);
    split_fc<<<(128 * Hdim + 255) / 256, 256>>>(fcwH, fcwL, fcW);
    bias_prep<<<4, 256>>>(bias0, bias1, b0ih, b0hh, b1ih, b1hh);

    const dim3 grid_rnn(Bsz / TM, Hdim / TN);   // 16 x 8 = 128 CTAs
    const int  KCHUNKS = Hdim / KC;             // 32

    // ---- t=0 ----
    l0_init<<<(Bsz * Hdim + 255) / 256, 256>>>(h0hi, h0lo, x, w0ih, bias0);
    gemm_k<false><<<grid_rnn, 256, SMEM_TOTAL>>>(
        hshi, hslo, nullptr,
        h0hi, h0lo, w1ihH, w1ihL, KCHUNKS,
        nullptr, nullptr, nullptr, nullptr, 0,
        bias1, nullptr, nullptr, 0);

    // ---- t = 1..95 ----
    for (int t = 1; t < Lseq; ++t) {
        const int cur = t & 1, prv = cur ^ 1;
        __nv_bfloat16* h0hc = h0hi + (size_t)cur * Bsz * Hdim;
        __nv_bfloat16* h0lc = h0lo + (size_t)cur * Bsz * Hdim;
        const __nv_bfloat16* h0hp = h0hi + (size_t)prv * Bsz * Hdim;
        const __nv_bfloat16* h0lp = h0lo + (size_t)prv * Bsz * Hdim;
        const bool last = (t == Lseq - 1);

        // layer0: h0 = tanh(h0_prev@W0hh^T + x_t*w0ih + bias0)
        gemm_k<false><<<grid_rnn, 256, SMEM_TOTAL>>>(
            h0hc, h0lc, last ? h0f : nullptr,
            h0hp, h0lp, w0hhH, w0hhL, KCHUNKS,
            nullptr, nullptr, nullptr, nullptr, 0,
            bias0, x, w0ih, t);

        // layer1: h1 = tanh(h0@W1ih^T + h1_prev@W1hh^T + bias1)
        __nv_bfloat16* hsh = hshi + (size_t)t * Bsz * Hdim;
        __nv_bfloat16* hsl = hslo + (size_t)t * Bsz * Hdim;
        gemm_k<false><<<grid_rnn, 256, SMEM_TOTAL>>>(
            hsh, hsl, last ? h1f : nullptr,
            h0hc, h0lc, w1ihH, w1ihL, KCHUNKS,
            hshi + (size_t)(t - 1) * Bsz * Hdim,
            hslo + (size_t)(t - 1) * Bsz * Hdim, w1hhH, w1hhL, KCHUNKS,
            bias1, nullptr, nullptr, t);
    }

    // ---- FC over full h1 history -> logits (permuted to [b, t, v]) ----
    gemm_k<true><<<dim3(Lseq * Bsz / TM, 1), 256, SMEM_TOTAL>>>(
        nullptr, nullptr, out,
        hshi, hslo, fcwH, fcwL, KCHUNKS,
        nullptr, nullptr, nullptr, nullptr, 0,
        fcb, nullptr, nullptr, 0);

    // ---- sequential probability patch + hidden tail ----
    adjust_kernel<<<Bsz / 8, 256>>>(out);
    hidden_copy<<<(Bsz * Hdim + 255) / 256, 256>>>(
        out + (size_t)Bsz * Lseq * Vsz, h0f, h1f);
}